// round 10
// baseline (speedup 1.0000x reference)
#include <cuda_runtime.h>
#include <cuda_fp16.h>

// Problem constants (fixed by the reference)
#define N_USERS   100000
#define N_ITEMS   50000
#define FDIM      64
#define N_LAYERS  3
#define NE_MAX    3200000

#define NUF (N_USERS * FDIM)   // 6,400,000
#define NIF (N_ITEMS * FDIM)   // 3,200,000
#define NTOT (N_USERS + N_ITEMS)
#define SCAN_BLOCKS ((NTOT + 1023) / 1024)   // 147

// ---------------------------------------------------------------------------
// Device scratch (static globals; no runtime allocation)
// ---------------------------------------------------------------------------
__device__ __half g_u16[N_LAYERS + 1][NUF];   // 51.2 MB
__device__ __half g_i16[N_LAYERS + 1][NIF];   // 25.6 MB

__device__ int2  g_csr_ui[NE_MAX];            // (item_col, val bits) keyed by user
__device__ int2  g_csr_iu[NE_MAX];            // (user_col, val bits) keyed by item

__device__ int   g_ptr_u[N_USERS + 1];
__device__ int   g_ptr_i[N_ITEMS + 1];
__device__ int   g_next_u[N_USERS];
__device__ int   g_next_i[N_ITEMS];
__device__ int   g_aux[256];                  // per-block scan aggregates

// ---------------------------------------------------------------------------
// Kernel 1: fused init — fp32 -> fp16 embedding convert (layer 0 tables)
// and zero the histogram arrays. Thread roles by index range.
// ---------------------------------------------------------------------------
__global__ void k_init(const float4* __restrict__ emb_u,
                       const float4* __restrict__ emb_i) {
    const int nuf4 = NUF / 4;
    const int nif4 = NIF / 4;
    int t = blockIdx.x * blockDim.x + threadIdx.x;

    if (t < nuf4) {
        float4 v = emb_u[t];
        __half2* p = reinterpret_cast<__half2*>(g_u16[0]);
        p[2 * t]     = __floats2half2_rn(v.x, v.y);
        p[2 * t + 1] = __floats2half2_rn(v.z, v.w);
        return;
    }
    t -= nuf4;
    if (t < nif4) {
        float4 v = emb_i[t];
        __half2* p = reinterpret_cast<__half2*>(g_i16[0]);
        p[2 * t]     = __floats2half2_rn(v.x, v.y);
        p[2 * t + 1] = __floats2half2_rn(v.z, v.w);
        return;
    }
    t -= nif4;
    if (t <= N_USERS) { g_ptr_u[t] = 0; return; }
    t -= (N_USERS + 1);
    if (t <= N_ITEMS) { g_ptr_i[t] = 0; }
}

// ---------------------------------------------------------------------------
// Kernel 2: degree histogram
// ---------------------------------------------------------------------------
__global__ void k_hist(const int* __restrict__ edge_user,
                       const int* __restrict__ edge_item, int ne) {
    int t = blockIdx.x * blockDim.x + threadIdx.x;
    if (t >= ne) return;
    atomicAdd(&g_ptr_u[edge_user[t]], 1);
    atomicAdd(&g_ptr_i[edge_item[t]], 1);
}

// ---------------------------------------------------------------------------
// Kernel 3a: per-block aggregates of the concatenated [u | i] histogram.
// Spin-free: no inter-block dependencies.
// ---------------------------------------------------------------------------
__global__ void k_scanA() {
    int i = blockIdx.x * 1024 + threadIdx.x;
    int v = 0;
    if (i < N_USERS)    v = g_ptr_u[i];
    else if (i < NTOT)  v = g_ptr_i[i - N_USERS];

    #pragma unroll
    for (int off = 16; off > 0; off >>= 1)
        v += __shfl_xor_sync(0xffffffffu, v, off);

    __shared__ int ws[32];
    int warp = threadIdx.x >> 5;
    int lane = threadIdx.x & 31;
    if (lane == 0) ws[warp] = v;
    __syncthreads();
    if (threadIdx.x < 32) {
        int t = ws[threadIdx.x];
        #pragma unroll
        for (int off = 16; off > 0; off >>= 1)
            t += __shfl_xor_sync(0xffffffffu, t, off);
        if (threadIdx.x == 0) g_aux[blockIdx.x] = t;
    }
}

// ---------------------------------------------------------------------------
// Kernel 3b: each block redundantly scans the 147 aggregates, block-scans its
// own tile, and writes the final exclusive offsets (+ cursor copies + tails).
// The item part is rebased by -ne (sum of user counts == ne).
// ---------------------------------------------------------------------------
__global__ void k_scanB(int ne) {
    __shared__ int s[1024];
    __shared__ int aux_s[256];
    int b = blockIdx.x;
    int i = b * 1024 + threadIdx.x;

    if (threadIdx.x < 256)
        aux_s[threadIdx.x] = (threadIdx.x < SCAN_BLOCKS) ? g_aux[threadIdx.x] : 0;

    int v = 0;
    if (i < N_USERS)    v = g_ptr_u[i];
    else if (i < NTOT)  v = g_ptr_i[i - N_USERS];
    s[threadIdx.x] = v;
    __syncthreads();

    // inclusive scan of aggregates (256-wide, threads < 256 do the work)
    #pragma unroll
    for (int off = 1; off < 256; off <<= 1) {
        int t = 0;
        if (threadIdx.x < 256 && threadIdx.x >= off) t = aux_s[threadIdx.x - off];
        __syncthreads();
        if (threadIdx.x < 256) aux_s[threadIdx.x] += t;
        __syncthreads();
    }

    // inclusive scan of the tile
    #pragma unroll
    for (int off = 1; off < 1024; off <<= 1) {
        int t = (threadIdx.x >= off) ? s[threadIdx.x - off] : 0;
        __syncthreads();
        s[threadIdx.x] += t;
        __syncthreads();
    }

    int prefix = (b == 0) ? 0 : aux_s[b - 1];
    int fin = prefix + s[threadIdx.x] - v;   // exclusive

    if (i < N_USERS) {
        g_ptr_u[i] = fin;
        g_next_u[i] = fin;
    } else if (i < NTOT) {
        int j = i - N_USERS;
        int w = fin - ne;
        g_ptr_i[j] = w;
        g_next_i[j] = w;
    }
    if (i == 0) {
        g_ptr_u[N_USERS] = ne;
        g_ptr_i[N_ITEMS] = ne;
    }
}

// ---------------------------------------------------------------------------
// Kernel 4: scatter edges into both CSR structures
// ---------------------------------------------------------------------------
__global__ void k_build(const int* __restrict__ edge_user,
                        const int* __restrict__ edge_item,
                        const float* __restrict__ vals_ui,
                        const float* __restrict__ vals_iu, int ne) {
    int t = blockIdx.x * blockDim.x + threadIdx.x;
    if (t >= ne) return;
    int u = edge_user[t];
    int i = edge_item[t];
    int pu = atomicAdd(&g_next_u[u], 1);
    g_csr_ui[pu] = make_int2(i, __float_as_int(vals_ui[t]));
    int pi = atomicAdd(&g_next_i[i], 1);
    g_csr_iu[pi] = make_int2(u, __float_as_int(vals_iu[t]));
}

// ---------------------------------------------------------------------------
// Kernel 5: CSR SpMM (fp16 tables, fp32 accumulate), one warp per dest row.
// Lane layout: grp = lane>>3 (neighbor slot 0..3), sub = lane&7 (16B chunk).
// Each warp LDG.128 services 4 edges. Double-buffered CSR staging removes the
// per-batch L2-latency bubble; 16-edge unroll keeps 4 LDG.128 in flight.
// ---------------------------------------------------------------------------
__global__ void __launch_bounds__(256) k_spmm(const float* __restrict__ du,
                                              const float* __restrict__ di,
                                              int k) {
    __shared__ int2 stage[8][32];
    int warp = threadIdx.x >> 5;
    int lane = threadIdx.x & 31;
    int grp  = lane >> 3;     // 0..3: neighbor slot
    int sub  = lane & 7;      // 0..7: 16B chunk within the 128B row
    int row = blockIdx.x * 8 + warp;

    const int2* csr; const int* ptr;
    const uint4* src4; const uint4* prev4; const float* dvec;
    uint4* dst4; int r;

    if (row < N_USERS) {
        r = row; csr = g_csr_ui; ptr = g_ptr_u;
        src4  = reinterpret_cast<const uint4*>(g_i16[k - 1]);
        prev4 = reinterpret_cast<const uint4*>(g_u16[k - 1]);
        dvec = du;
        dst4  = reinterpret_cast<uint4*>(g_u16[k]);
    } else {
        r = row - N_USERS;
        if (r >= N_ITEMS) return;
        csr = g_csr_iu; ptr = g_ptr_i;
        src4  = reinterpret_cast<const uint4*>(g_u16[k - 1]);
        prev4 = reinterpret_cast<const uint4*>(g_i16[k - 1]);
        dvec = di;
        dst4  = reinterpret_cast<uint4*>(g_i16[k]);
    }

    int beg = ptr[r];
    int end = ptr[r + 1];

    float a0 = 0.f, a1 = 0.f, a2 = 0.f, a3 = 0.f;
    float a4 = 0.f, a5 = 0.f, a6 = 0.f, a7 = 0.f;

    // Prefetch first batch of CSR entries into registers
    int2 cur = make_int2(0, 0);
    if (beg + lane < end) cur = csr[beg + lane];

    for (int bb = beg; bb < end; bb += 32) {
        int n = min(32, end - bb);
        stage[warp][lane] = cur;
        __syncwarp();

        // Prefetch next batch while this one computes
        int2 nxt = make_int2(0, 0);
        if (bb + 32 + lane < end) nxt = csr[bb + 32 + lane];

        int j = 0;
        // 16 edges per iteration: four LDG.128 in flight per warp
        for (; j + 16 <= n; j += 16) {
            int2 e0 = stage[warp][j + grp];
            int2 e1 = stage[warp][j + 4 + grp];
            int2 e2 = stage[warp][j + 8 + grp];
            int2 e3 = stage[warp][j + 12 + grp];
            uint4 q0 = src4[e0.x * 8 + sub];
            uint4 q1 = src4[e1.x * 8 + sub];
            uint4 q2 = src4[e2.x * 8 + sub];
            uint4 q3 = src4[e3.x * 8 + sub];
            float w0 = __int_as_float(e0.y);
            float w1 = __int_as_float(e1.y);
            float w2 = __int_as_float(e2.y);
            float w3 = __int_as_float(e3.y);
            {
                float2 f0 = __half22float2(*reinterpret_cast<__half2*>(&q0.x));
                float2 f1 = __half22float2(*reinterpret_cast<__half2*>(&q0.y));
                float2 f2 = __half22float2(*reinterpret_cast<__half2*>(&q0.z));
                float2 f3 = __half22float2(*reinterpret_cast<__half2*>(&q0.w));
                a0 = fmaf(w0, f0.x, a0); a1 = fmaf(w0, f0.y, a1);
                a2 = fmaf(w0, f1.x, a2); a3 = fmaf(w0, f1.y, a3);
                a4 = fmaf(w0, f2.x, a4); a5 = fmaf(w0, f2.y, a5);
                a6 = fmaf(w0, f3.x, a6); a7 = fmaf(w0, f3.y, a7);
            }
            {
                float2 f0 = __half22float2(*reinterpret_cast<__half2*>(&q1.x));
                float2 f1 = __half22float2(*reinterpret_cast<__half2*>(&q1.y));
                float2 f2 = __half22float2(*reinterpret_cast<__half2*>(&q1.z));
                float2 f3 = __half22float2(*reinterpret_cast<__half2*>(&q1.w));
                a0 = fmaf(w1, f0.x, a0); a1 = fmaf(w1, f0.y, a1);
                a2 = fmaf(w1, f1.x, a2); a3 = fmaf(w1, f1.y, a3);
                a4 = fmaf(w1, f2.x, a4); a5 = fmaf(w1, f2.y, a5);
                a6 = fmaf(w1, f3.x, a6); a7 = fmaf(w1, f3.y, a7);
            }
            {
                float2 f0 = __half22float2(*reinterpret_cast<__half2*>(&q2.x));
                float2 f1 = __half22float2(*reinterpret_cast<__half2*>(&q2.y));
                float2 f2 = __half22float2(*reinterpret_cast<__half2*>(&q2.z));
                float2 f3 = __half22float2(*reinterpret_cast<__half2*>(&q2.w));
                a0 = fmaf(w2, f0.x, a0); a1 = fmaf(w2, f0.y, a1);
                a2 = fmaf(w2, f1.x, a2); a3 = fmaf(w2, f1.y, a3);
                a4 = fmaf(w2, f2.x, a4); a5 = fmaf(w2, f2.y, a5);
                a6 = fmaf(w2, f3.x, a6); a7 = fmaf(w2, f3.y, a7);
            }
            {
                float2 f0 = __half22float2(*reinterpret_cast<__half2*>(&q3.x));
                float2 f1 = __half22float2(*reinterpret_cast<__half2*>(&q3.y));
                float2 f2 = __half22float2(*reinterpret_cast<__half2*>(&q3.z));
                float2 f3 = __half22float2(*reinterpret_cast<__half2*>(&q3.w));
                a0 = fmaf(w3, f0.x, a0); a1 = fmaf(w3, f0.y, a1);
                a2 = fmaf(w3, f1.x, a2); a3 = fmaf(w3, f1.y, a3);
                a4 = fmaf(w3, f2.x, a4); a5 = fmaf(w3, f2.y, a5);
                a6 = fmaf(w3, f3.x, a6); a7 = fmaf(w3, f3.y, a7);
            }
        }
        // 8-edge step
        for (; j + 8 <= n; j += 8) {
            int2 e0 = stage[warp][j + grp];
            int2 e1 = stage[warp][j + 4 + grp];
            uint4 q0 = src4[e0.x * 8 + sub];
            uint4 q1 = src4[e1.x * 8 + sub];
            float w0 = __int_as_float(e0.y);
            float w1 = __int_as_float(e1.y);
            {
                float2 f0 = __half22float2(*reinterpret_cast<__half2*>(&q0.x));
                float2 f1 = __half22float2(*reinterpret_cast<__half2*>(&q0.y));
                float2 f2 = __half22float2(*reinterpret_cast<__half2*>(&q0.z));
                float2 f3 = __half22float2(*reinterpret_cast<__half2*>(&q0.w));
                a0 = fmaf(w0, f0.x, a0); a1 = fmaf(w0, f0.y, a1);
                a2 = fmaf(w0, f1.x, a2); a3 = fmaf(w0, f1.y, a3);
                a4 = fmaf(w0, f2.x, a4); a5 = fmaf(w0, f2.y, a5);
                a6 = fmaf(w0, f3.x, a6); a7 = fmaf(w0, f3.y, a7);
            }
            {
                float2 f0 = __half22float2(*reinterpret_cast<__half2*>(&q1.x));
                float2 f1 = __half22float2(*reinterpret_cast<__half2*>(&q1.y));
                float2 f2 = __half22float2(*reinterpret_cast<__half2*>(&q1.z));
                float2 f3 = __half22float2(*reinterpret_cast<__half2*>(&q1.w));
                a0 = fmaf(w1, f0.x, a0); a1 = fmaf(w1, f0.y, a1);
                a2 = fmaf(w1, f1.x, a2); a3 = fmaf(w1, f1.y, a3);
                a4 = fmaf(w1, f2.x, a4); a5 = fmaf(w1, f2.y, a5);
                a6 = fmaf(w1, f3.x, a6); a7 = fmaf(w1, f3.y, a7);
            }
        }
        // tail: groups of 4 with weight-guard for the ragged end
        for (; j < n; j += 4) {
            int idx = j + grp;
            int2 e = stage[warp][idx < n ? idx : 0];
            float w = (idx < n) ? __int_as_float(e.y) : 0.f;
            uint4 q = src4[e.x * 8 + sub];
            float2 f0 = __half22float2(*reinterpret_cast<__half2*>(&q.x));
            float2 f1 = __half22float2(*reinterpret_cast<__half2*>(&q.y));
            float2 f2 = __half22float2(*reinterpret_cast<__half2*>(&q.z));
            float2 f3 = __half22float2(*reinterpret_cast<__half2*>(&q.w));
            a0 = fmaf(w, f0.x, a0); a1 = fmaf(w, f0.y, a1);
            a2 = fmaf(w, f1.x, a2); a3 = fmaf(w, f1.y, a3);
            a4 = fmaf(w, f2.x, a4); a5 = fmaf(w, f2.y, a5);
            a6 = fmaf(w, f3.x, a6); a7 = fmaf(w, f3.y, a7);
        }
        __syncwarp();
        cur = nxt;
    }

    // reduce across the 4 neighbor groups (lanes differing in bits 3,4)
    #pragma unroll
    for (int off = 8; off <= 16; off <<= 1) {
        a0 += __shfl_xor_sync(0xffffffffu, a0, off);
        a1 += __shfl_xor_sync(0xffffffffu, a1, off);
        a2 += __shfl_xor_sync(0xffffffffu, a2, off);
        a3 += __shfl_xor_sync(0xffffffffu, a3, off);
        a4 += __shfl_xor_sync(0xffffffffu, a4, off);
        a5 += __shfl_xor_sync(0xffffffffu, a5, off);
        a6 += __shfl_xor_sync(0xffffffffu, a6, off);
        a7 += __shfl_xor_sync(0xffffffffu, a7, off);
    }

    // epilogue: lanes 0..7 add the diagonal term and store their 16B chunk
    if (grp == 0) {
        float dd = dvec[r];
        uint4 pq = prev4[r * 8 + sub];
        float2 p0 = __half22float2(*reinterpret_cast<__half2*>(&pq.x));
        float2 p1 = __half22float2(*reinterpret_cast<__half2*>(&pq.y));
        float2 p2 = __half22float2(*reinterpret_cast<__half2*>(&pq.z));
        float2 p3 = __half22float2(*reinterpret_cast<__half2*>(&pq.w));
        a0 = fmaf(dd, p0.x, a0); a1 = fmaf(dd, p0.y, a1);
        a2 = fmaf(dd, p1.x, a2); a3 = fmaf(dd, p1.y, a3);
        a4 = fmaf(dd, p2.x, a4); a5 = fmaf(dd, p2.y, a5);
        a6 = fmaf(dd, p3.x, a6); a7 = fmaf(dd, p3.y, a7);
        uint4 o;
        __half2 h;
        h = __floats2half2_rn(a0, a1); o.x = *reinterpret_cast<unsigned*>(&h);
        h = __floats2half2_rn(a2, a3); o.y = *reinterpret_cast<unsigned*>(&h);
        h = __floats2half2_rn(a4, a5); o.z = *reinterpret_cast<unsigned*>(&h);
        h = __floats2half2_rn(a6, a7); o.w = *reinterpret_cast<unsigned*>(&h);
        dst4[r * 8 + sub] = o;
    }
}

// ---------------------------------------------------------------------------
// Kernel 6: output gather. out layout [seg(3)][batch][256], fp32.
// ---------------------------------------------------------------------------
__global__ void k_out_gather(const int* __restrict__ users,
                             const int* __restrict__ pos_item,
                             const int* __restrict__ neg_item,
                             const float* __restrict__ emb_user,
                             const float* __restrict__ emb_item,
                             float4* __restrict__ out, int batch) {
    int t = blockIdx.x * blockDim.x + threadIdx.x;
    int total = 3 * batch * 64;
    if (t >= total) return;

    int q   = t & 63;
    int b   = (t >> 6) % batch;
    int seg = t / (batch * 64);
    int k   = q >> 4;
    int f4  = q & 15;

    int row;
    bool is_user = (seg == 0);
    if (is_user)        row = users[b];
    else if (seg == 1)  row = pos_item[b];
    else                row = neg_item[b];

    if (k == 0) {
        const float* tab = is_user ? emb_user : emb_item;
        out[t] = *reinterpret_cast<const float4*>(tab + (size_t)row * FDIM + f4 * 4);
    } else {
        const __half* tab = is_user ? g_u16[k] : g_i16[k];
        uint2 raw = *reinterpret_cast<const uint2*>(tab + (size_t)row * FDIM + f4 * 4);
        __half2 h0 = *reinterpret_cast<const __half2*>(&raw.x);
        __half2 h1 = *reinterpret_cast<const __half2*>(&raw.y);
        float2 a = __half22float2(h0);
        float2 c = __half22float2(h1);
        out[t] = make_float4(a.x, a.y, c.x, c.y);
    }
}

// ---------------------------------------------------------------------------
// kernel_launch: 9 launches
// ---------------------------------------------------------------------------
extern "C" void kernel_launch(void* const* d_in, const int* in_sizes, int n_in,
                              void* d_out, int out_size) {
    const int*   edge_user = (const int*)  d_in[0];
    const int*   edge_item = (const int*)  d_in[1];
    const float* vals_ui   = (const float*)d_in[2];
    const float* vals_iu   = (const float*)d_in[3];
    const float* d_users   = (const float*)d_in[4];
    const float* d_items   = (const float*)d_in[5];
    const float* emb_user  = (const float*)d_in[6];
    const float* emb_item  = (const float*)d_in[7];
    const int*   users     = (const int*)  d_in[8];
    const int*   pos_item  = (const int*)  d_in[9];
    const int*   neg_item  = (const int*)  d_in[10];

    const int ne    = in_sizes[0];
    const int batch = in_sizes[8];
    const int TPB   = 256;

    // 0) convert embeddings + zero histograms
    {
        int total = NUF / 4 + NIF / 4 + (N_USERS + 1) + (N_ITEMS + 1);
        k_init<<<(total + TPB - 1) / TPB, TPB>>>(
            (const float4*)emb_user, (const float4*)emb_item);
    }
    // 1) histogram
    k_hist<<<(ne + TPB - 1) / TPB, TPB>>>(edge_user, edge_item, ne);
    // 2-3) spin-free two-phase scan
    k_scanA<<<SCAN_BLOCKS, 1024>>>();
    k_scanB<<<SCAN_BLOCKS, 1024>>>(ne);
    // 4) CSR scatter
    k_build<<<(ne + TPB - 1) / TPB, TPB>>>(edge_user, edge_item, vals_ui, vals_iu, ne);

    // 5-7) 3 layers of fused SpMM + diagonal
    int spmm_blocks = (N_USERS + N_ITEMS + 7) / 8;
    for (int k = 1; k <= N_LAYERS; k++) {
        k_spmm<<<spmm_blocks, TPB>>>(d_users, d_items, k);
    }

    // 8) output gather
    int total = 3 * batch * 64;
    k_out_gather<<<(total + TPB - 1) / TPB, TPB>>>(
        users, pos_item, neg_item, emb_user, emb_item, (float4*)d_out, batch);
}

// round 11
// speedup vs baseline: 1.0173x; 1.0173x over previous
#include <cuda_runtime.h>
#include <cuda_fp16.h>

// Problem constants (fixed by the reference)
#define N_USERS   100000
#define N_ITEMS   50000
#define FDIM      64
#define N_LAYERS  3
#define NE_MAX    3200000

#define NUF (N_USERS * FDIM)   // 6,400,000
#define NIF (N_ITEMS * FDIM)   // 3,200,000
#define NTOT (N_USERS + N_ITEMS)
#define SCAN_BLOCKS ((NTOT + 1023) / 1024)   // 147

// ---------------------------------------------------------------------------
// Device scratch (static globals; no runtime allocation)
// ---------------------------------------------------------------------------
__device__ __half g_u16[N_LAYERS + 1][NUF];   // 51.2 MB
__device__ __half g_i16[N_LAYERS + 1][NIF];   // 25.6 MB

__device__ int2  g_csr_ui[NE_MAX];            // (item_col, val bits) keyed by user
__device__ int2  g_csr_iu[NE_MAX];            // (user_col, val bits) keyed by item

__device__ int   g_ptr_u[N_USERS + 1];
__device__ int   g_ptr_i[N_ITEMS + 1];
__device__ int   g_aux[256];                  // per-block scan aggregates

// ---------------------------------------------------------------------------
// Kernel 1: fused init — fp32 -> fp16 embedding convert (layer 0 tables)
// and zero the histogram arrays. Thread roles by index range.
// ---------------------------------------------------------------------------
__global__ void k_init(const float4* __restrict__ emb_u,
                       const float4* __restrict__ emb_i) {
    const int nuf4 = NUF / 4;
    const int nif4 = NIF / 4;
    int t = blockIdx.x * blockDim.x + threadIdx.x;

    if (t < nuf4) {
        float4 v = emb_u[t];
        __half2* p = reinterpret_cast<__half2*>(g_u16[0]);
        p[2 * t]     = __floats2half2_rn(v.x, v.y);
        p[2 * t + 1] = __floats2half2_rn(v.z, v.w);
        return;
    }
    t -= nuf4;
    if (t < nif4) {
        float4 v = emb_i[t];
        __half2* p = reinterpret_cast<__half2*>(g_i16[0]);
        p[2 * t]     = __floats2half2_rn(v.x, v.y);
        p[2 * t + 1] = __floats2half2_rn(v.z, v.w);
        return;
    }
    t -= nif4;
    if (t <= N_USERS) { g_ptr_u[t] = 0; return; }
    t -= (N_USERS + 1);
    if (t <= N_ITEMS) { g_ptr_i[t] = 0; }
}

// ---------------------------------------------------------------------------
// Kernel 2: degree histogram
// ---------------------------------------------------------------------------
__global__ void k_hist(const int* __restrict__ edge_user,
                       const int* __restrict__ edge_item, int ne) {
    int t = blockIdx.x * blockDim.x + threadIdx.x;
    if (t >= ne) return;
    atomicAdd(&g_ptr_u[edge_user[t]], 1);
    atomicAdd(&g_ptr_i[edge_item[t]], 1);
}

// ---------------------------------------------------------------------------
// Kernel 3a: per-block aggregates of the concatenated [u | i] histogram.
// ---------------------------------------------------------------------------
__global__ void k_scanA() {
    int i = blockIdx.x * 1024 + threadIdx.x;
    int v = 0;
    if (i < N_USERS)    v = g_ptr_u[i];
    else if (i < NTOT)  v = g_ptr_i[i - N_USERS];

    #pragma unroll
    for (int off = 16; off > 0; off >>= 1)
        v += __shfl_xor_sync(0xffffffffu, v, off);

    __shared__ int ws[32];
    int warp = threadIdx.x >> 5;
    int lane = threadIdx.x & 31;
    if (lane == 0) ws[warp] = v;
    __syncthreads();
    if (threadIdx.x < 32) {
        int t = ws[threadIdx.x];
        #pragma unroll
        for (int off = 16; off > 0; off >>= 1)
            t += __shfl_xor_sync(0xffffffffu, t, off);
        if (threadIdx.x == 0) g_aux[blockIdx.x] = t;
    }
}

// ---------------------------------------------------------------------------
// Kernel 3b: each block redundantly scans the 147 aggregates, block-scans its
// own tile, and writes the final exclusive offsets. The item part is rebased
// by -ne (sum of user counts == ne). No cursor copy: k_build bumps g_ptr
// itself, and k_spmm uses the shifted semantics (ptr[r] = end of row r).
// ---------------------------------------------------------------------------
__global__ void k_scanB(int ne) {
    __shared__ int s[1024];
    __shared__ int aux_s[256];
    int b = blockIdx.x;
    int i = b * 1024 + threadIdx.x;

    if (threadIdx.x < 256)
        aux_s[threadIdx.x] = (threadIdx.x < SCAN_BLOCKS) ? g_aux[threadIdx.x] : 0;

    int v = 0;
    if (i < N_USERS)    v = g_ptr_u[i];
    else if (i < NTOT)  v = g_ptr_i[i - N_USERS];
    s[threadIdx.x] = v;
    __syncthreads();

    // inclusive scan of aggregates (256-wide)
    #pragma unroll
    for (int off = 1; off < 256; off <<= 1) {
        int t = 0;
        if (threadIdx.x < 256 && threadIdx.x >= off) t = aux_s[threadIdx.x - off];
        __syncthreads();
        if (threadIdx.x < 256) aux_s[threadIdx.x] += t;
        __syncthreads();
    }

    // inclusive scan of the tile
    #pragma unroll
    for (int off = 1; off < 1024; off <<= 1) {
        int t = (threadIdx.x >= off) ? s[threadIdx.x - off] : 0;
        __syncthreads();
        s[threadIdx.x] += t;
        __syncthreads();
    }

    int prefix = (b == 0) ? 0 : aux_s[b - 1];
    int fin = prefix + s[threadIdx.x] - v;   // exclusive

    if (i < N_USERS)    g_ptr_u[i] = fin;
    else if (i < NTOT)  g_ptr_i[i - N_USERS] = fin - ne;
}

// ---------------------------------------------------------------------------
// Kernel 4: scatter edges into both CSR structures. Uses g_ptr as the cursor;
// after this kernel, g_ptr[r] = END of row r (start = g_ptr[r-1], row 0 = 0).
// ---------------------------------------------------------------------------
__global__ void k_build(const int* __restrict__ edge_user,
                        const int* __restrict__ edge_item,
                        const float* __restrict__ vals_ui,
                        const float* __restrict__ vals_iu, int ne) {
    int t = blockIdx.x * blockDim.x + threadIdx.x;
    if (t >= ne) return;
    int u = edge_user[t];
    int i = edge_item[t];
    int pu = atomicAdd(&g_ptr_u[u], 1);
    g_csr_ui[pu] = make_int2(i, __float_as_int(vals_ui[t]));
    int pi = atomicAdd(&g_ptr_i[i], 1);
    g_csr_iu[pi] = make_int2(u, __float_as_int(vals_iu[t]));
}

// ---------------------------------------------------------------------------
// Kernel 5: CSR SpMM (fp16 tables, fp32 accumulate), one warp per dest row.
// Lane layout: grp = lane>>3 (neighbor slot 0..3), sub = lane&7 (16B chunk).
// Each warp LDG.128 services 4 edges. Pointer-light loop body (only csr +
// src4 live) for occupancy; epilogue pointers recomputed from is_user.
// ---------------------------------------------------------------------------
__global__ void __launch_bounds__(256, 6) k_spmm(const float* __restrict__ du,
                                                 const float* __restrict__ di,
                                                 int k) {
    __shared__ int2 stage[8][32];
    int warp = threadIdx.x >> 5;
    int lane = threadIdx.x & 31;
    int grp  = lane >> 3;     // 0..3: neighbor slot
    int sub  = lane & 7;      // 0..7: 16B chunk within the 128B row
    int row = blockIdx.x * 8 + warp;

    const int2* csr;
    const uint4* src4;
    int r;
    bool is_user;
    int beg, end;

    if (row < N_USERS) {
        is_user = true;
        r = row;
        csr = g_csr_ui;
        src4 = reinterpret_cast<const uint4*>(g_i16[k - 1]);
        end = g_ptr_u[r];
        beg = (r == 0) ? 0 : g_ptr_u[r - 1];
    } else {
        r = row - N_USERS;
        if (r >= N_ITEMS) return;
        is_user = false;
        csr = g_csr_iu;
        src4 = reinterpret_cast<const uint4*>(g_u16[k - 1]);
        end = g_ptr_i[r];
        beg = (r == 0) ? 0 : g_ptr_i[r - 1];
    }

    float a0 = 0.f, a1 = 0.f, a2 = 0.f, a3 = 0.f;
    float a4 = 0.f, a5 = 0.f, a6 = 0.f, a7 = 0.f;

    for (int bb = beg; bb < end; bb += 32) {
        int n = min(32, end - bb);
        if (lane < n) stage[warp][lane] = csr[bb + lane];
        __syncwarp();

        int j = 0;
        // 8 edges per iteration: two LDG.128 in flight per warp
        for (; j + 8 <= n; j += 8) {
            int2 e0 = stage[warp][j + grp];
            int2 e1 = stage[warp][j + 4 + grp];
            uint4 q0 = src4[e0.x * 8 + sub];
            uint4 q1 = src4[e1.x * 8 + sub];
            float w0 = __int_as_float(e0.y);
            float w1 = __int_as_float(e1.y);
            {
                float2 f0 = __half22float2(*reinterpret_cast<__half2*>(&q0.x));
                float2 f1 = __half22float2(*reinterpret_cast<__half2*>(&q0.y));
                float2 f2 = __half22float2(*reinterpret_cast<__half2*>(&q0.z));
                float2 f3 = __half22float2(*reinterpret_cast<__half2*>(&q0.w));
                a0 = fmaf(w0, f0.x, a0); a1 = fmaf(w0, f0.y, a1);
                a2 = fmaf(w0, f1.x, a2); a3 = fmaf(w0, f1.y, a3);
                a4 = fmaf(w0, f2.x, a4); a5 = fmaf(w0, f2.y, a5);
                a6 = fmaf(w0, f3.x, a6); a7 = fmaf(w0, f3.y, a7);
            }
            {
                float2 f0 = __half22float2(*reinterpret_cast<__half2*>(&q1.x));
                float2 f1 = __half22float2(*reinterpret_cast<__half2*>(&q1.y));
                float2 f2 = __half22float2(*reinterpret_cast<__half2*>(&q1.z));
                float2 f3 = __half22float2(*reinterpret_cast<__half2*>(&q1.w));
                a0 = fmaf(w1, f0.x, a0); a1 = fmaf(w1, f0.y, a1);
                a2 = fmaf(w1, f1.x, a2); a3 = fmaf(w1, f1.y, a3);
                a4 = fmaf(w1, f2.x, a4); a5 = fmaf(w1, f2.y, a5);
                a6 = fmaf(w1, f3.x, a6); a7 = fmaf(w1, f3.y, a7);
            }
        }
        // tail: groups of 4 with weight-guard for the ragged end
        for (; j < n; j += 4) {
            int idx = j + grp;
            int2 e = stage[warp][idx < n ? idx : 0];
            float w = (idx < n) ? __int_as_float(e.y) : 0.f;
            uint4 q = src4[e.x * 8 + sub];
            float2 f0 = __half22float2(*reinterpret_cast<__half2*>(&q.x));
            float2 f1 = __half22float2(*reinterpret_cast<__half2*>(&q.y));
            float2 f2 = __half22float2(*reinterpret_cast<__half2*>(&q.z));
            float2 f3 = __half22float2(*reinterpret_cast<__half2*>(&q.w));
            a0 = fmaf(w, f0.x, a0); a1 = fmaf(w, f0.y, a1);
            a2 = fmaf(w, f1.x, a2); a3 = fmaf(w, f1.y, a3);
            a4 = fmaf(w, f2.x, a4); a5 = fmaf(w, f2.y, a5);
            a6 = fmaf(w, f3.x, a6); a7 = fmaf(w, f3.y, a7);
        }
        __syncwarp();
    }

    // reduce across the 4 neighbor groups (lanes differing in bits 3,4)
    #pragma unroll
    for (int off = 8; off <= 16; off <<= 1) {
        a0 += __shfl_xor_sync(0xffffffffu, a0, off);
        a1 += __shfl_xor_sync(0xffffffffu, a1, off);
        a2 += __shfl_xor_sync(0xffffffffu, a2, off);
        a3 += __shfl_xor_sync(0xffffffffu, a3, off);
        a4 += __shfl_xor_sync(0xffffffffu, a4, off);
        a5 += __shfl_xor_sync(0xffffffffu, a5, off);
        a6 += __shfl_xor_sync(0xffffffffu, a6, off);
        a7 += __shfl_xor_sync(0xffffffffu, a7, off);
    }

    // epilogue: lanes 0..7 add the diagonal term and store their 16B chunk.
    // Pointers recomputed here so they are not live across the main loop.
    if (grp == 0) {
        const float* dvec  = is_user ? du : di;
        const uint4* prev4 = is_user ? reinterpret_cast<const uint4*>(g_u16[k - 1])
                                     : reinterpret_cast<const uint4*>(g_i16[k - 1]);
        uint4*       dst4  = is_user ? reinterpret_cast<uint4*>(g_u16[k])
                                     : reinterpret_cast<uint4*>(g_i16[k]);
        float dd = dvec[r];
        uint4 pq = prev4[r * 8 + sub];
        float2 p0 = __half22float2(*reinterpret_cast<__half2*>(&pq.x));
        float2 p1 = __half22float2(*reinterpret_cast<__half2*>(&pq.y));
        float2 p2 = __half22float2(*reinterpret_cast<__half2*>(&pq.z));
        float2 p3 = __half22float2(*reinterpret_cast<__half2*>(&pq.w));
        a0 = fmaf(dd, p0.x, a0); a1 = fmaf(dd, p0.y, a1);
        a2 = fmaf(dd, p1.x, a2); a3 = fmaf(dd, p1.y, a3);
        a4 = fmaf(dd, p2.x, a4); a5 = fmaf(dd, p2.y, a5);
        a6 = fmaf(dd, p3.x, a6); a7 = fmaf(dd, p3.y, a7);
        uint4 o;
        __half2 h;
        h = __floats2half2_rn(a0, a1); o.x = *reinterpret_cast<unsigned*>(&h);
        h = __floats2half2_rn(a2, a3); o.y = *reinterpret_cast<unsigned*>(&h);
        h = __floats2half2_rn(a4, a5); o.z = *reinterpret_cast<unsigned*>(&h);
        h = __floats2half2_rn(a6, a7); o.w = *reinterpret_cast<unsigned*>(&h);
        dst4[r * 8 + sub] = o;
    }
}

// ---------------------------------------------------------------------------
// Kernel 6: output gather. out layout [seg(3)][batch][256], fp32.
// ---------------------------------------------------------------------------
__global__ void k_out_gather(const int* __restrict__ users,
                             const int* __restrict__ pos_item,
                             const int* __restrict__ neg_item,
                             const float* __restrict__ emb_user,
                             const float* __restrict__ emb_item,
                             float4* __restrict__ out, int batch) {
    int t = blockIdx.x * blockDim.x + threadIdx.x;
    int total = 3 * batch * 64;
    if (t >= total) return;

    int q   = t & 63;
    int b   = (t >> 6) % batch;
    int seg = t / (batch * 64);
    int k   = q >> 4;
    int f4  = q & 15;

    int row;
    bool is_user = (seg == 0);
    if (is_user)        row = users[b];
    else if (seg == 1)  row = pos_item[b];
    else                row = neg_item[b];

    if (k == 0) {
        const float* tab = is_user ? emb_user : emb_item;
        out[t] = *reinterpret_cast<const float4*>(tab + (size_t)row * FDIM + f4 * 4);
    } else {
        const __half* tab = is_user ? g_u16[k] : g_i16[k];
        uint2 raw = *reinterpret_cast<const uint2*>(tab + (size_t)row * FDIM + f4 * 4);
        __half2 h0 = *reinterpret_cast<const __half2*>(&raw.x);
        __half2 h1 = *reinterpret_cast<const __half2*>(&raw.y);
        float2 a = __half22float2(h0);
        float2 c = __half22float2(h1);
        out[t] = make_float4(a.x, a.y, c.x, c.y);
    }
}

// ---------------------------------------------------------------------------
// kernel_launch: 9 launches
// ---------------------------------------------------------------------------
extern "C" void kernel_launch(void* const* d_in, const int* in_sizes, int n_in,
                              void* d_out, int out_size) {
    const int*   edge_user = (const int*)  d_in[0];
    const int*   edge_item = (const int*)  d_in[1];
    const float* vals_ui   = (const float*)d_in[2];
    const float* vals_iu   = (const float*)d_in[3];
    const float* d_users   = (const float*)d_in[4];
    const float* d_items   = (const float*)d_in[5];
    const float* emb_user  = (const float*)d_in[6];
    const float* emb_item  = (const float*)d_in[7];
    const int*   users     = (const int*)  d_in[8];
    const int*   pos_item  = (const int*)  d_in[9];
    const int*   neg_item  = (const int*)  d_in[10];

    const int ne    = in_sizes[0];
    const int batch = in_sizes[8];
    const int TPB   = 256;

    // 0) convert embeddings + zero histograms
    {
        int total = NUF / 4 + NIF / 4 + (N_USERS + 1) + (N_ITEMS + 1);
        k_init<<<(total + TPB - 1) / TPB, TPB>>>(
            (const float4*)emb_user, (const float4*)emb_item);
    }
    // 1) histogram
    k_hist<<<(ne + TPB - 1) / TPB, TPB>>>(edge_user, edge_item, ne);
    // 2-3) spin-free two-phase scan
    k_scanA<<<SCAN_BLOCKS, 1024>>>();
    k_scanB<<<SCAN_BLOCKS, 1024>>>(ne);
    // 4) CSR scatter (bumps g_ptr; afterwards ptr[r] = end of row r)
    k_build<<<(ne + TPB - 1) / TPB, TPB>>>(edge_user, edge_item, vals_ui, vals_iu, ne);

    // 5-7) 3 layers of fused SpMM + diagonal
    int spmm_blocks = (N_USERS + N_ITEMS + 7) / 8;
    for (int k = 1; k <= N_LAYERS; k++) {
        k_spmm<<<spmm_blocks, TPB>>>(d_users, d_items, k);
    }

    // 8) output gather
    int total = 3 * batch * 64;
    k_out_gather<<<(total + TPB - 1) / TPB, TPB>>>(
        users, pos_item, neg_item, emb_user, emb_item, (float4*)d_out, batch);
}

// round 13
// speedup vs baseline: 1.1755x; 1.1555x over previous
#include <cuda_runtime.h>
#include <cuda_fp16.h>

// Problem constants (fixed by the reference)
#define N_USERS   100000
#define N_ITEMS   50000
#define FDIM      64
#define N_LAYERS  3
#define NE_MAX    3200000
#define BATCH_MAX 16384

#define NUF (N_USERS * FDIM)   // 6,400,000
#define NIF (N_ITEMS * FDIM)   // 3,200,000
#define NTOT (N_USERS + N_ITEMS)
#define SCAN_BLOCKS ((NTOT + 1023) / 1024)   // 147

// ---------------------------------------------------------------------------
// Device scratch (static globals; no runtime allocation)
// ---------------------------------------------------------------------------
__device__ __half g_u16[N_LAYERS + 1][NUF];   // 51.2 MB
__device__ __half g_i16[N_LAYERS + 1][NIF];   // 25.6 MB

__device__ int2  g_csr_ui[NE_MAX];            // (item_col, val bits) keyed by user
__device__ int2  g_csr_iu[NE_MAX];            // (user_col, val bits) keyed by item

__device__ int   g_ptr_u[N_USERS + 1];
__device__ int   g_ptr_i[N_ITEMS + 1];
__device__ int   g_aux[256];                  // per-block scan aggregates

// Layer-3 sparsity: only rows actually read by the output gather
__device__ int   g_flag_u[N_USERS];
__device__ int   g_flag_i[N_ITEMS];
__device__ int   g_list_u[BATCH_MAX];
__device__ int   g_list_i[2 * BATCH_MAX];
__device__ int   g_cnt_u;
__device__ int   g_cnt_i;

// ---------------------------------------------------------------------------
// Kernel 1: fused init — fp32 -> fp16 embedding convert (layer 0 tables),
// zero histograms, zero layer-3 row flags + counters.
// ---------------------------------------------------------------------------
__global__ void k_init(const float4* __restrict__ emb_u,
                       const float4* __restrict__ emb_i) {
    const int nuf4 = NUF / 4;
    const int nif4 = NIF / 4;
    int t = blockIdx.x * blockDim.x + threadIdx.x;

    if (t < nuf4) {
        float4 v = emb_u[t];
        __half2* p = reinterpret_cast<__half2*>(g_u16[0]);
        p[2 * t]     = __floats2half2_rn(v.x, v.y);
        p[2 * t + 1] = __floats2half2_rn(v.z, v.w);
        return;
    }
    t -= nuf4;
    if (t < nif4) {
        float4 v = emb_i[t];
        __half2* p = reinterpret_cast<__half2*>(g_i16[0]);
        p[2 * t]     = __floats2half2_rn(v.x, v.y);
        p[2 * t + 1] = __floats2half2_rn(v.z, v.w);
        return;
    }
    t -= nif4;
    if (t <= N_USERS) { g_ptr_u[t] = 0; return; }
    t -= (N_USERS + 1);
    if (t <= N_ITEMS) { g_ptr_i[t] = 0; return; }
    t -= (N_ITEMS + 1);
    if (t < N_USERS) { g_flag_u[t] = 0; return; }
    t -= N_USERS;
    if (t < N_ITEMS) { g_flag_i[t] = 0; return; }
    t -= N_ITEMS;
    if (t == 0) { g_cnt_u = 0; g_cnt_i = 0; }
}

// ---------------------------------------------------------------------------
// Kernel 2: mark + compact the layer-3 destination rows.
// t in [0, batch): user rows; t in [batch, 3*batch): pos/neg item rows.
// ---------------------------------------------------------------------------
__global__ void k_mark(const int* __restrict__ users,
                       const int* __restrict__ pos_item,
                       const int* __restrict__ neg_item, int batch) {
    int t = blockIdx.x * blockDim.x + threadIdx.x;
    if (t < batch) {
        int r = users[t];
        if (atomicExch(&g_flag_u[r], 1) == 0)
            g_list_u[atomicAdd(&g_cnt_u, 1)] = r;
    } else if (t < 3 * batch) {
        int s = t - batch;
        int r = (s < batch) ? pos_item[s] : neg_item[s - batch];
        if (atomicExch(&g_flag_i[r], 1) == 0)
            g_list_i[atomicAdd(&g_cnt_i, 1)] = r;
    }
}

// ---------------------------------------------------------------------------
// Kernel 3: degree histogram
// ---------------------------------------------------------------------------
__global__ void k_hist(const int* __restrict__ edge_user,
                       const int* __restrict__ edge_item, int ne) {
    int t = blockIdx.x * blockDim.x + threadIdx.x;
    if (t >= ne) return;
    atomicAdd(&g_ptr_u[edge_user[t]], 1);
    atomicAdd(&g_ptr_i[edge_item[t]], 1);
}

// ---------------------------------------------------------------------------
// Kernel 4a: per-block aggregates of the concatenated [u | i] histogram.
// ---------------------------------------------------------------------------
__global__ void k_scanA() {
    int i = blockIdx.x * 1024 + threadIdx.x;
    int v = 0;
    if (i < N_USERS)    v = g_ptr_u[i];
    else if (i < NTOT)  v = g_ptr_i[i - N_USERS];

    #pragma unroll
    for (int off = 16; off > 0; off >>= 1)
        v += __shfl_xor_sync(0xffffffffu, v, off);

    __shared__ int ws[32];
    int warp = threadIdx.x >> 5;
    int lane = threadIdx.x & 31;
    if (lane == 0) ws[warp] = v;
    __syncthreads();
    if (threadIdx.x < 32) {
        int t = ws[threadIdx.x];
        #pragma unroll
        for (int off = 16; off > 0; off >>= 1)
            t += __shfl_xor_sync(0xffffffffu, t, off);
        if (threadIdx.x == 0) g_aux[blockIdx.x] = t;
    }
}

// ---------------------------------------------------------------------------
// Kernel 4b: redundant aggregate scan + tile scan -> final exclusive offsets.
// Item part rebased by -ne. k_build bumps g_ptr (afterwards ptr[r] = row end).
// ---------------------------------------------------------------------------
__global__ void k_scanB(int ne) {
    __shared__ int s[1024];
    __shared__ int aux_s[256];
    int b = blockIdx.x;
    int i = b * 1024 + threadIdx.x;

    if (threadIdx.x < 256)
        aux_s[threadIdx.x] = (threadIdx.x < SCAN_BLOCKS) ? g_aux[threadIdx.x] : 0;

    int v = 0;
    if (i < N_USERS)    v = g_ptr_u[i];
    else if (i < NTOT)  v = g_ptr_i[i - N_USERS];
    s[threadIdx.x] = v;
    __syncthreads();

    #pragma unroll
    for (int off = 1; off < 256; off <<= 1) {
        int t = 0;
        if (threadIdx.x < 256 && threadIdx.x >= off) t = aux_s[threadIdx.x - off];
        __syncthreads();
        if (threadIdx.x < 256) aux_s[threadIdx.x] += t;
        __syncthreads();
    }

    #pragma unroll
    for (int off = 1; off < 1024; off <<= 1) {
        int t = (threadIdx.x >= off) ? s[threadIdx.x - off] : 0;
        __syncthreads();
        s[threadIdx.x] += t;
        __syncthreads();
    }

    int prefix = (b == 0) ? 0 : aux_s[b - 1];
    int fin = prefix + s[threadIdx.x] - v;   // exclusive

    if (i < N_USERS)    g_ptr_u[i] = fin;
    else if (i < NTOT)  g_ptr_i[i - N_USERS] = fin - ne;
}

// ---------------------------------------------------------------------------
// Kernel 5: scatter edges into both CSR structures (g_ptr as cursor).
// ---------------------------------------------------------------------------
__global__ void k_build(const int* __restrict__ edge_user,
                        const int* __restrict__ edge_item,
                        const float* __restrict__ vals_ui,
                        const float* __restrict__ vals_iu, int ne) {
    int t = blockIdx.x * blockDim.x + threadIdx.x;
    if (t >= ne) return;
    int u = edge_user[t];
    int i = edge_item[t];
    int pu = atomicAdd(&g_ptr_u[u], 1);
    g_csr_ui[pu] = make_int2(i, __float_as_int(vals_ui[t]));
    int pi = atomicAdd(&g_ptr_i[i], 1);
    g_csr_iu[pi] = make_int2(u, __float_as_int(vals_iu[t]));
}

// ---------------------------------------------------------------------------
// SpMM row body (shared by full-layer and layer-3 kernels).
// Lane layout: grp = lane>>3 (neighbor slot), sub = lane&7 (16B chunk).
// ---------------------------------------------------------------------------
__device__ __forceinline__ void spmm_row(int r, bool is_user, int k,
                                         const float* du, const float* di,
                                         int2* stage_w, int lane, int grp, int sub) {
    const int2* csr;
    const uint4* src4;
    int beg, end;

    if (is_user) {
        csr = g_csr_ui;
        src4 = reinterpret_cast<const uint4*>(g_i16[k - 1]);
        end = g_ptr_u[r];
        beg = (r == 0) ? 0 : g_ptr_u[r - 1];
    } else {
        csr = g_csr_iu;
        src4 = reinterpret_cast<const uint4*>(g_u16[k - 1]);
        end = g_ptr_i[r];
        beg = (r == 0) ? 0 : g_ptr_i[r - 1];
    }

    float a0 = 0.f, a1 = 0.f, a2 = 0.f, a3 = 0.f;
    float a4 = 0.f, a5 = 0.f, a6 = 0.f, a7 = 0.f;

    for (int bb = beg; bb < end; bb += 32) {
        int n = min(32, end - bb);
        if (lane < n) stage_w[lane] = csr[bb + lane];
        __syncwarp();

        int j = 0;
        for (; j + 8 <= n; j += 8) {
            int2 e0 = stage_w[j + grp];
            int2 e1 = stage_w[j + 4 + grp];
            uint4 q0 = src4[e0.x * 8 + sub];
            uint4 q1 = src4[e1.x * 8 + sub];
            float w0 = __int_as_float(e0.y);
            float w1 = __int_as_float(e1.y);
            {
                float2 f0 = __half22float2(*reinterpret_cast<__half2*>(&q0.x));
                float2 f1 = __half22float2(*reinterpret_cast<__half2*>(&q0.y));
                float2 f2 = __half22float2(*reinterpret_cast<__half2*>(&q0.z));
                float2 f3 = __half22float2(*reinterpret_cast<__half2*>(&q0.w));
                a0 = fmaf(w0, f0.x, a0); a1 = fmaf(w0, f0.y, a1);
                a2 = fmaf(w0, f1.x, a2); a3 = fmaf(w0, f1.y, a3);
                a4 = fmaf(w0, f2.x, a4); a5 = fmaf(w0, f2.y, a5);
                a6 = fmaf(w0, f3.x, a6); a7 = fmaf(w0, f3.y, a7);
            }
            {
                float2 f0 = __half22float2(*reinterpret_cast<__half2*>(&q1.x));
                float2 f1 = __half22float2(*reinterpret_cast<__half2*>(&q1.y));
                float2 f2 = __half22float2(*reinterpret_cast<__half2*>(&q1.z));
                float2 f3 = __half22float2(*reinterpret_cast<__half2*>(&q1.w));
                a0 = fmaf(w1, f0.x, a0); a1 = fmaf(w1, f0.y, a1);
                a2 = fmaf(w1, f1.x, a2); a3 = fmaf(w1, f1.y, a3);
                a4 = fmaf(w1, f2.x, a4); a5 = fmaf(w1, f2.y, a5);
                a6 = fmaf(w1, f3.x, a6); a7 = fmaf(w1, f3.y, a7);
            }
        }
        for (; j < n; j += 4) {
            int idx = j + grp;
            int2 e = stage_w[idx < n ? idx : 0];
            float w = (idx < n) ? __int_as_float(e.y) : 0.f;
            uint4 q = src4[e.x * 8 + sub];
            float2 f0 = __half22float2(*reinterpret_cast<__half2*>(&q.x));
            float2 f1 = __half22float2(*reinterpret_cast<__half2*>(&q.y));
            float2 f2 = __half22float2(*reinterpret_cast<__half2*>(&q.z));
            float2 f3 = __half22float2(*reinterpret_cast<__half2*>(&q.w));
            a0 = fmaf(w, f0.x, a0); a1 = fmaf(w, f0.y, a1);
            a2 = fmaf(w, f1.x, a2); a3 = fmaf(w, f1.y, a3);
            a4 = fmaf(w, f2.x, a4); a5 = fmaf(w, f2.y, a5);
            a6 = fmaf(w, f3.x, a6); a7 = fmaf(w, f3.y, a7);
        }
        __syncwarp();
    }

    #pragma unroll
    for (int off = 8; off <= 16; off <<= 1) {
        a0 += __shfl_xor_sync(0xffffffffu, a0, off);
        a1 += __shfl_xor_sync(0xffffffffu, a1, off);
        a2 += __shfl_xor_sync(0xffffffffu, a2, off);
        a3 += __shfl_xor_sync(0xffffffffu, a3, off);
        a4 += __shfl_xor_sync(0xffffffffu, a4, off);
        a5 += __shfl_xor_sync(0xffffffffu, a5, off);
        a6 += __shfl_xor_sync(0xffffffffu, a6, off);
        a7 += __shfl_xor_sync(0xffffffffu, a7, off);
    }

    if (grp == 0) {
        const float* dvec  = is_user ? du : di;
        const uint4* prev4 = is_user ? reinterpret_cast<const uint4*>(g_u16[k - 1])
                                     : reinterpret_cast<const uint4*>(g_i16[k - 1]);
        uint4*       dst4  = is_user ? reinterpret_cast<uint4*>(g_u16[k])
                                     : reinterpret_cast<uint4*>(g_i16[k]);
        float dd = dvec[r];
        uint4 pq = prev4[r * 8 + sub];
        float2 p0 = __half22float2(*reinterpret_cast<__half2*>(&pq.x));
        float2 p1 = __half22float2(*reinterpret_cast<__half2*>(&pq.y));
        float2 p2 = __half22float2(*reinterpret_cast<__half2*>(&pq.z));
        float2 p3 = __half22float2(*reinterpret_cast<__half2*>(&pq.w));
        a0 = fmaf(dd, p0.x, a0); a1 = fmaf(dd, p0.y, a1);
        a2 = fmaf(dd, p1.x, a2); a3 = fmaf(dd, p1.y, a3);
        a4 = fmaf(dd, p2.x, a4); a5 = fmaf(dd, p2.y, a5);
        a6 = fmaf(dd, p3.x, a6); a7 = fmaf(dd, p3.y, a7);
        uint4 o;
        __half2 h;
        h = __floats2half2_rn(a0, a1); o.x = *reinterpret_cast<unsigned*>(&h);
        h = __floats2half2_rn(a2, a3); o.y = *reinterpret_cast<unsigned*>(&h);
        h = __floats2half2_rn(a4, a5); o.z = *reinterpret_cast<unsigned*>(&h);
        h = __floats2half2_rn(a6, a7); o.w = *reinterpret_cast<unsigned*>(&h);
        dst4[r * 8 + sub] = o;
    }
}

// ---------------------------------------------------------------------------
// Kernel 6: full-layer SpMM (layers 1, 2) — one warp per destination row.
// ---------------------------------------------------------------------------
__global__ void __launch_bounds__(256, 6) k_spmm(const float* __restrict__ du,
                                                 const float* __restrict__ di,
                                                 int k) {
    __shared__ int2 stage[8][32];
    int warp = threadIdx.x >> 5;
    int lane = threadIdx.x & 31;
    int row = blockIdx.x * 8 + warp;

    int r; bool is_user;
    if (row < N_USERS) { r = row; is_user = true; }
    else {
        r = row - N_USERS;
        if (r >= N_ITEMS) return;
        is_user = false;
    }
    spmm_row(r, is_user, k, du, di, stage[warp], lane, lane >> 3, lane & 7);
}

// ---------------------------------------------------------------------------
// Kernel 7: layer-3 SpMM over only the rows the output gather reads.
// Warp slots [0, batch): user list; [batch, 3*batch): item list.
// ---------------------------------------------------------------------------
__global__ void __launch_bounds__(256, 6) k_spmm_l3(const float* __restrict__ du,
                                                    const float* __restrict__ di,
                                                    int batch) {
    __shared__ int2 stage[8][32];
    int warp = threadIdx.x >> 5;
    int lane = threadIdx.x & 31;
    int slot = blockIdx.x * 8 + warp;

    int r; bool is_user;
    if (slot < batch) {
        if (slot >= g_cnt_u) return;
        r = g_list_u[slot];
        is_user = true;
    } else {
        int s = slot - batch;
        if (s >= g_cnt_i) return;
        r = g_list_i[s];
        is_user = false;
    }
    spmm_row(r, is_user, N_LAYERS, du, di, stage[warp], lane, lane >> 3, lane & 7);
}

// ---------------------------------------------------------------------------
// Kernel 8: output gather. out layout [seg(3)][batch][256], fp32.
// ---------------------------------------------------------------------------
__global__ void k_out_gather(const int* __restrict__ users,
                             const int* __restrict__ pos_item,
                             const int* __restrict__ neg_item,
                             const float* __restrict__ emb_user,
                             const float* __restrict__ emb_item,
                             float4* __restrict__ out, int batch) {
    int t = blockIdx.x * blockDim.x + threadIdx.x;
    int total = 3 * batch * 64;
    if (t >= total) return;

    int q   = t & 63;
    int b   = (t >> 6) % batch;
    int seg = t / (batch * 64);
    int k   = q >> 4;
    int f4  = q & 15;

    int row;
    bool is_user = (seg == 0);
    if (is_user)        row = users[b];
    else if (seg == 1)  row = pos_item[b];
    else                row = neg_item[b];

    if (k == 0) {
        const float* tab = is_user ? emb_user : emb_item;
        out[t] = *reinterpret_cast<const float4*>(tab + (size_t)row * FDIM + f4 * 4);
    } else {
        const __half* tab = is_user ? g_u16[k] : g_i16[k];
        uint2 raw = *reinterpret_cast<const uint2*>(tab + (size_t)row * FDIM + f4 * 4);
        __half2 h0 = *reinterpret_cast<const __half2*>(&raw.x);
        __half2 h1 = *reinterpret_cast<const __half2*>(&raw.y);
        float2 a = __half22float2(h0);
        float2 c = __half22float2(h1);
        out[t] = make_float4(a.x, a.y, c.x, c.y);
    }
}

// ---------------------------------------------------------------------------
// kernel_launch: 10 launches
// ---------------------------------------------------------------------------
extern "C" void kernel_launch(void* const* d_in, const int* in_sizes, int n_in,
                              void* d_out, int out_size) {
    const int*   edge_user = (const int*)  d_in[0];
    const int*   edge_item = (const int*)  d_in[1];
    const float* vals_ui   = (const float*)d_in[2];
    const float* vals_iu   = (const float*)d_in[3];
    const float* d_users   = (const float*)d_in[4];
    const float* d_items   = (const float*)d_in[5];
    const float* emb_user  = (const float*)d_in[6];
    const float* emb_item  = (const float*)d_in[7];
    const int*   users     = (const int*)  d_in[8];
    const int*   pos_item  = (const int*)  d_in[9];
    const int*   neg_item  = (const int*)  d_in[10];

    const int ne    = in_sizes[0];
    const int batch = in_sizes[8];
    const int TPB   = 256;

    // 0) convert embeddings + zero histograms/flags/counters
    {
        int total = NUF / 4 + NIF / 4 + (N_USERS + 1) + (N_ITEMS + 1)
                  + N_USERS + N_ITEMS + 1;
        k_init<<<(total + TPB - 1) / TPB, TPB>>>(
            (const float4*)emb_user, (const float4*)emb_item);
    }
    // 1) mark + compact layer-3 destination rows
    k_mark<<<(3 * batch + TPB - 1) / TPB, TPB>>>(users, pos_item, neg_item, batch);
    // 2) histogram
    k_hist<<<(ne + TPB - 1) / TPB, TPB>>>(edge_user, edge_item, ne);
    // 3-4) spin-free two-phase scan
    k_scanA<<<SCAN_BLOCKS, 1024>>>();
    k_scanB<<<SCAN_BLOCKS, 1024>>>(ne);
    // 5) CSR scatter (bumps g_ptr; afterwards ptr[r] = end of row r)
    k_build<<<(ne + TPB - 1) / TPB, TPB>>>(edge_user, edge_item, vals_ui, vals_iu, ne);

    // 6-7) full SpMM layers 1, 2
    int spmm_blocks = (N_USERS + N_ITEMS + 7) / 8;
    k_spmm<<<spmm_blocks, TPB>>>(d_users, d_items, 1);
    k_spmm<<<spmm_blocks, TPB>>>(d_users, d_items, 2);
    // 8) sparse layer 3 (only rows read by the gather)
    int l3_blocks = (3 * batch + 7) / 8;
    k_spmm_l3<<<l3_blocks, TPB>>>(d_users, d_items, batch);

    // 9) output gather
    int total = 3 * batch * 64;
    k_out_gather<<<(total + TPB - 1) / TPB, TPB>>>(
        users, pos_item, neg_item, emb_user, emb_item, (float4*)d_out, batch);
}